// round 5
// baseline (speedup 1.0000x reference)
#include <cuda_runtime.h>
#include <cuda_bf16.h>
#include <math.h>
#include <cstdint>

#define NROWS 8192
#define DDIM  64
#define MARGIN 1.1f
#define EPS 1e-8f
#define TILE 128
#define NTILES (NROWS / TILE)                // 64
#define NBLOCKS (NTILES * (NTILES + 1) / 2)  // 2080
#define NPREP NTILES                         // 64 prep blocks
#define NCLS 17
#define ROWB 144                             // padded smem row stride (bytes)

// Scratch (no allocs allowed).
__device__ __align__(16) __nv_bfloat16 g_xb[NROWS * DDIM];  // class-sorted rows
__device__ int      g_cls[NROWS];            // class-sorted labels
__device__ int      g_bh[NPREP][NCLS];       // per-block class histograms
__device__ double   g_accum;                 // zero-init; last block resets
__device__ unsigned g_ph1, g_ph2, g_done;    // phase counters (reset each run)

__device__ __forceinline__ uint32_t smem_u32(const void* p) {
    uint32_t a;
    asm("{ .reg .u64 t; cvta.to.shared.u64 t, %1; cvt.u32.u64 %0, t; }"
        : "=r"(a) : "l"(p));
    return a;
}

__device__ __forceinline__ void ldsm_x4(uint32_t& r0, uint32_t& r1,
                                        uint32_t& r2, uint32_t& r3,
                                        uint32_t addr) {
    asm volatile("ldmatrix.sync.aligned.m8n8.x4.shared.b16 {%0,%1,%2,%3}, [%4];"
                 : "=r"(r0), "=r"(r1), "=r"(r2), "=r"(r3) : "r"(addr));
}

__device__ __forceinline__ void mma_16816(float* c, const uint32_t* a,
                                          uint32_t b0, uint32_t b1) {
    asm volatile(
        "mma.sync.aligned.m16n8k16.row.col.f32.bf16.bf16.f32 "
        "{%0,%1,%2,%3}, {%4,%5,%6,%7}, {%8,%9}, {%0,%1,%2,%3};"
        : "+f"(c[0]), "+f"(c[1]), "+f"(c[2]), "+f"(c[3])
        : "r"(a[0]), "r"(a[1]), "r"(a[2]), "r"(a[3]), "r"(b0), "r"(b1));
}

__device__ __forceinline__ void spin_until(unsigned* ctr, unsigned target) {
    unsigned v;
    do {
        asm volatile("ld.acquire.gpu.u32 %0, [%1];" : "=r"(v) : "l"(ctr));
        if (v < target) __nanosleep(64);
    } while (v < target);
}

// ---------------------------------------------------------------------------
// One fused kernel.
// Blocks 0..63: normalize rows -> bf16, histogram classes, then (after
// device barrier 1) deterministically scatter rows into class-sorted order.
// All blocks: after device barrier 2, compute one upper-triangular 128x128
// Gram tile. Tiles provably free of same-class pairs (sorted layout!) use a
// select-free hinge epilogue; near-diagonal tiles use the exact compare
// epilogue. Last block finalizes the mean and resets state.
// ---------------------------------------------------------------------------
__global__ __launch_bounds__(256, 2) void fused_kernel(
    const float* __restrict__ x, const int* __restrict__ cls,
    float* __restrict__ out) {

    const int bid  = blockIdx.x;
    const int tid  = threadIdx.x;
    const int wid  = tid >> 5;
    const int lane = tid & 31;

    __shared__ __align__(16) char sA[TILE * ROWB];     // also: bf16 staging
    __shared__ __align__(16) char sB[TILE * ROWB];     // also: hist/prefix scratch
    __shared__ int   csi[TILE];                        // also: staged classes
    __shared__ int   csj[TILE];
    __shared__ float red[8];

    // ================= Phase A/B: prep blocks 0..63 ========================
    if (bid < NPREP) {
        // --- normalize (2 threads per row) into smem staging -------------
        __nv_bfloat16* stage = (__nv_bfloat16*)sA;     // 128 x 64 bf16 = 16KB
        int* shist   = (int*)sB;                       // [17]
        int* sprefix = (int*)(sB + 128);               // [17]
        int* sbase   = (int*)(sB + 256);               // [17]

        const int row  = (tid >> 1);                   // 0..127 (local)
        const int half = tid & 1;
        const float4* xr =
            (const float4*)(x + ((size_t)bid * TILE + row) * DDIM + half * 32);
        float4 v[8];
        #pragma unroll
        for (int i = 0; i < 8; i++) v[i] = xr[i];
        float s = 0.0f;
        #pragma unroll
        for (int i = 0; i < 8; i++)
            s += v[i].x * v[i].x + v[i].y * v[i].y +
                 v[i].z * v[i].z + v[i].w * v[i].w;
        s += __shfl_xor_sync(0xffffffffu, s, 1);
        float inv = 1.0f / fmaxf(sqrtf(s), EPS);
        __nv_bfloat16* dst = stage + row * DDIM + half * 32;
        #pragma unroll
        for (int i = 0; i < 8; i++) {
            __nv_bfloat162 p0 = {__float2bfloat16(v[i].x * inv),
                                 __float2bfloat16(v[i].y * inv)};
            __nv_bfloat162 p1 = {__float2bfloat16(v[i].z * inv),
                                 __float2bfloat16(v[i].w * inv)};
            *(__nv_bfloat162*)(dst + i * 4)     = p0;
            *(__nv_bfloat162*)(dst + i * 4 + 2) = p1;
        }
        if (half == 0) csi[row] = cls[bid * TILE + row];
        if (tid < NCLS) shist[tid] = 0;
        __syncthreads();

        // --- per-block class histogram ------------------------------------
        if (tid < TILE) atomicAdd(&shist[csi[tid]], 1);
        __syncthreads();
        if (tid < NCLS) g_bh[bid][tid] = shist[tid];
        if (tid == 0) { __threadfence(); atomicAdd(&g_ph1, 1u); }

        // --- wait for all histograms --------------------------------------
        if (tid == 0) spin_until(&g_ph1, NPREP);
        __syncthreads();

        // --- offsets: global prefix + this block's partial -----------------
        int partial = 0;
        if (tid < NCLS) {
            int colsum = 0;
            for (int b = 0; b < NPREP; b++) {
                int h = g_bh[b][tid];
                colsum += h;
                if (b < bid) partial += h;
            }
            shist[tid] = colsum;
        }
        __syncthreads();
        if (tid == 0) {
            int run = 0;
            for (int c = 0; c < NCLS; c++) { sprefix[c] = run; run += shist[c]; }
        }
        __syncthreads();
        if (tid < NCLS) sbase[tid] = sprefix[tid] + partial;
        __syncthreads();

        // --- deterministic rank + scatter ----------------------------------
        if (tid < TILE) {
            const int c = csi[tid];
            int rank = 0;
            for (int j = 0; j < tid; j++) rank += (csi[j] == c);
            const int pos = sbase[c] + rank;
            const uint4* src = (const uint4*)(stage + tid * DDIM);
            uint4* dstg = (uint4*)(g_xb + (size_t)pos * DDIM);
            #pragma unroll
            for (int q = 0; q < 8; q++) dstg[q] = src[q];
            g_cls[pos] = c;
        }
        __syncthreads();
        if (tid == 0) { __threadfence(); atomicAdd(&g_ph2, 1u); }
    }

    // ================= Device barrier 2: sorted data ready =================
    if (tid == 0) spin_until(&g_ph2, NPREP);
    __syncthreads();

    // ================= Main pass: one triangular tile ======================
    int bi = (int)((129.0f - sqrtf(16641.0f - 8.0f * (float)bid)) * 0.5f);
    while (bi * (129 - bi) / 2 > bid) bi--;
    while ((bi + 1) * (128 - bi) / 2 <= bid) bi++;
    const int bj = bi + (bid - bi * (129 - bi) / 2);
    const bool diag = (bi == bj);

    // Sorted layout: tile contains a same-class pair iff the last class of
    // band bi equals the first class of band bj (exact, since classes sorted).
    const bool near_ =
        diag || (g_cls[bi * TILE + TILE - 1] == g_cls[bj * TILE]);

    const uint4* Ag = (const uint4*)(g_xb + (size_t)bi * TILE * DDIM);
    #pragma unroll
    for (int r = 0; r < 4; r++) {
        int idx = tid + r * 256;
        int row = idx >> 3;
        int ch  = idx & 7;
        *(uint4*)(sA + row * ROWB + ch * 16) = Ag[idx];
    }
    if (!diag) {
        const uint4* Bg = (const uint4*)(g_xb + (size_t)bj * TILE * DDIM);
        #pragma unroll
        for (int r = 0; r < 4; r++) {
            int idx = tid + r * 256;
            int row = idx >> 3;
            int ch  = idx & 7;
            *(uint4*)(sB + row * ROWB + ch * 16) = Bg[idx];
        }
    }
    if (near_) {
        if (tid < TILE) csi[tid]        = g_cls[bi * TILE + tid];
        else            csj[tid - TILE] = g_cls[bj * TILE + (tid - TILE)];
    }
    __syncthreads();

    const uint32_t a_base = smem_u32(sA);
    const uint32_t b_base = diag ? a_base : smem_u32(sB);

    const int wm = wid & 3;
    const int wn = wid >> 2;
    const uint32_t a_lane_off =
        (uint32_t)((wm * 32 + (lane & 15)) * ROWB + ((lane >> 4) << 4));
    const uint32_t b_lane_off =
        (uint32_t)((wn * 64 + (lane & 7) + ((lane >> 4) << 3)) * ROWB +
                   (((lane >> 3) & 1) << 4));

    float c[2][8][4];
    #pragma unroll
    for (int m = 0; m < 2; m++)
        #pragma unroll
        for (int n = 0; n < 8; n++)
            #pragma unroll
            for (int e = 0; e < 4; e++) c[m][n][e] = 0.0f;

    #pragma unroll
    for (int k = 0; k < 4; k++) {
        uint32_t a[2][4];
        #pragma unroll
        for (int m = 0; m < 2; m++)
            ldsm_x4(a[m][0], a[m][1], a[m][2], a[m][3],
                    a_base + a_lane_off + m * 16 * ROWB + k * 32);
        uint32_t b[8][2];
        #pragma unroll
        for (int q = 0; q < 4; q++) {
            uint32_t r0, r1, r2, r3;
            ldsm_x4(r0, r1, r2, r3,
                    b_base + b_lane_off + q * 16 * ROWB + k * 32);
            b[q * 2 + 0][0] = r0; b[q * 2 + 0][1] = r1;
            b[q * 2 + 1][0] = r2; b[q * 2 + 1][1] = r3;
        }
        #pragma unroll
        for (int m = 0; m < 2; m++)
            #pragma unroll
            for (int n = 0; n < 8; n++)
                mma_16816(c[m][n], a[m], b[n][0], b[n][1]);
    }

    // ----------------- Epilogue --------------------------------------------
    const float MC = MARGIN - 1.0f;
    float lsum;
    if (!near_) {
        // Select-free hinge: no same-class pairs in this tile.
        float l0 = 0.0f, l1 = 0.0f;
        #pragma unroll
        for (int m = 0; m < 2; m++)
            #pragma unroll
            for (int n = 0; n < 8; n++) {
                l0 += fmaxf(c[m][n][0] + MC, 0.0f);
                l1 += fmaxf(c[m][n][1] + MC, 0.0f);
                l0 += fmaxf(c[m][n][2] + MC, 0.0f);
                l1 += fmaxf(c[m][n][3] + MC, 0.0f);
            }
        lsum = l0 + l1;
    } else {
        const int* cj_src = diag ? csi : csj;
        const int quad = lane >> 2;
        const int tq   = lane & 3;
        float l0 = 0.0f, l1 = 0.0f;
        #pragma unroll
        for (int m = 0; m < 2; m++) {
            const int ci0 = csi[wm * 32 + m * 16 + quad];
            const int ci1 = csi[wm * 32 + m * 16 + quad + 8];
            #pragma unroll
            for (int n = 0; n < 8; n++) {
                const int colb = wn * 64 + n * 8 + tq * 2;
                const int cj0  = cj_src[colb];
                const int cj1  = cj_src[colb + 1];
                float v0 = c[m][n][0], v1 = c[m][n][1];
                float v2 = c[m][n][2], v3 = c[m][n][3];
                l0 += (ci0 == cj0) ? (1.0f - v0) : fmaxf(v0 + MC, 0.0f);
                l1 += (ci0 == cj1) ? (1.0f - v1) : fmaxf(v1 + MC, 0.0f);
                l0 += (ci1 == cj0) ? (1.0f - v2) : fmaxf(v2 + MC, 0.0f);
                l1 += (ci1 == cj1) ? (1.0f - v3) : fmaxf(v3 + MC, 0.0f);
            }
        }
        lsum = l0 + l1;
    }
    if (!diag) lsum *= 2.0f;     // symmetric tile counted once

    // ----------------- Reduce + finalize ------------------------------------
    #pragma unroll
    for (int o = 16; o; o >>= 1) lsum += __shfl_xor_sync(0xffffffffu, lsum, o);
    if (lane == 0) red[wid] = lsum;
    __syncthreads();
    if (tid == 0) {
        float t = 0.0f;
        #pragma unroll
        for (int w = 0; w < 8; w++) t += red[w];
        atomicAdd(&g_accum, (double)t);
        __threadfence();
        unsigned old = atomicAdd(&g_done, 1u);
        if (old == (unsigned)(NBLOCKS - 1)) {
            double a = atomicAdd(&g_accum, 0.0);
            out[0] = (float)(a / ((double)NROWS * (double)NROWS));
            g_accum = 0.0;
            g_done  = 0u;
            g_ph1   = 0u;
            g_ph2   = 0u;
        }
    }
}

extern "C" void kernel_launch(void* const* d_in, const int* in_sizes, int n_in,
                              void* d_out, int out_size) {
    const float* bottleneck = (const float*)d_in[0];
    const int*   class_map  = (const int*)d_in[1];
    float*       out        = (float*)d_out;
    fused_kernel<<<NBLOCKS, 256>>>(bottleneck, class_map, out);
}

// round 6
// speedup vs baseline: 1.2796x; 1.2796x over previous
#include <cuda_runtime.h>
#include <cuda_bf16.h>
#include <math.h>
#include <cstdint>

#define NROWS 8192
#define DDIM  64
#define MARGIN 1.1f
#define EPS 1e-8f
#define TILE 128
#define NTILES (NROWS / TILE)     // 64
#define NPREP  NTILES             // 64 prep blocks
#define NGROUPS 544               // sum over bi of ceil((64-bi)/4)
#define ROWB 144                  // padded smem row stride (bytes)
#define BUFB (TILE * ROWB)        // 18432 bytes per tile buffer
// dsm layout: A | B0 | B1 | B2 | csi[128] | csj[512] | red[8]
#define SMEM_TOTAL (4 * BUFB + (128 + 512) * 4 + 32)

// Scratch (no allocs allowed).
__device__ __align__(16) __nv_bfloat16 g_xb[NROWS * DDIM];
__device__ double   g_accum;          // zero-init; last block resets
__device__ unsigned g_prep_done;      // idem
__device__ unsigned g_done_ctr;       // idem

__device__ __forceinline__ uint32_t smem_u32(const void* p) {
    uint32_t a;
    asm("{ .reg .u64 t; cvta.to.shared.u64 t, %1; cvt.u32.u64 %0, t; }"
        : "=r"(a) : "l"(p));
    return a;
}

__device__ __forceinline__ void ldsm_x4(uint32_t& r0, uint32_t& r1,
                                        uint32_t& r2, uint32_t& r3,
                                        uint32_t addr) {
    asm volatile("ldmatrix.sync.aligned.m8n8.x4.shared.b16 {%0,%1,%2,%3}, [%4];"
                 : "=r"(r0), "=r"(r1), "=r"(r2), "=r"(r3) : "r"(addr));
}

__device__ __forceinline__ void mma_16816(float* c, const uint32_t* a,
                                          uint32_t b0, uint32_t b1) {
    asm volatile(
        "mma.sync.aligned.m16n8k16.row.col.f32.bf16.bf16.f32 "
        "{%0,%1,%2,%3}, {%4,%5,%6,%7}, {%8,%9}, {%0,%1,%2,%3};"
        : "+f"(c[0]), "+f"(c[1]), "+f"(c[2]), "+f"(c[3])
        : "r"(a[0]), "r"(a[1]), "r"(a[2]), "r"(a[3]), "r"(b0), "r"(b1));
}

__device__ __forceinline__ void cpa16(uint32_t dst, const void* src) {
    asm volatile("cp.async.cg.shared.global [%0], [%1], 16;"
                 :: "r"(dst), "l"(src) : "memory");
}
#define CPA_COMMIT() asm volatile("cp.async.commit_group;" ::: "memory")
#define CPA_WAIT(n)  asm volatile("cp.async.wait_group %0;" :: "n"(n) : "memory")

// ---------------------------------------------------------------------------
// One fused kernel. Blocks 0..63 also normalize -> bf16 (phase 1). All 544
// blocks then process a GROUP of up to 4 tiles sharing one A band:
// A loaded once, B tiles streamed with cp.async triple buffering; per-group
// single reduce + atomic. Last block finalizes mean and resets state.
// ---------------------------------------------------------------------------
__global__ __launch_bounds__(256, 2) void fused_kernel(
    const float* __restrict__ x, const int* __restrict__ cls,
    float* __restrict__ out) {

    extern __shared__ __align__(16) char dsm[];
    char*  sA   = dsm;
    char*  sB   = dsm + BUFB;                    // 3 buffers of BUFB
    int*   csi  = (int*)(dsm + 4 * BUFB);
    int*   csj  = csi + 128;                     // 4 x 128
    float* red  = (float*)(csj + 512);

    const int bid  = blockIdx.x;
    const int tid  = threadIdx.x;
    const int wid  = tid >> 5;
    const int lane = tid & 31;

    // ---------------- Phase 1: prep (normalize -> bf16), blocks 0..63 ------
    if (bid < NPREP) {
        int t    = bid * 256 + tid;
        int row  = t >> 1;
        int half = t & 1;
        const float4* xr = (const float4*)(x + (size_t)row * DDIM + half * 32);
        float4 v[8];
        #pragma unroll
        for (int i = 0; i < 8; i++) v[i] = xr[i];
        float s = 0.0f;
        #pragma unroll
        for (int i = 0; i < 8; i++)
            s += v[i].x * v[i].x + v[i].y * v[i].y +
                 v[i].z * v[i].z + v[i].w * v[i].w;
        s += __shfl_xor_sync(0xffffffffu, s, 1);
        float inv = 1.0f / fmaxf(sqrtf(s), EPS);
        __nv_bfloat16* dst = g_xb + (size_t)row * DDIM + half * 32;
        #pragma unroll
        for (int i = 0; i < 8; i++) {
            __nv_bfloat162 p0 = {__float2bfloat16(v[i].x * inv),
                                 __float2bfloat16(v[i].y * inv)};
            __nv_bfloat162 p1 = {__float2bfloat16(v[i].z * inv),
                                 __float2bfloat16(v[i].w * inv)};
            *(__nv_bfloat162*)(dst + i * 4)     = p0;
            *(__nv_bfloat162*)(dst + i * 4 + 2) = p1;
        }
        __syncthreads();
        if (tid == 0) { __threadfence(); atomicAdd(&g_prep_done, 1u); }
    }

    // ---------------- Device-wide wait for prep ----------------------------
    if (tid == 0) {
        unsigned v;
        do {
            asm volatile("ld.acquire.gpu.u32 %0, [%1];"
                         : "=r"(v) : "l"(&g_prep_done));
            if (v < (unsigned)NPREP) __nanosleep(64);
        } while (v < (unsigned)NPREP);
    }
    __syncthreads();

    // ---------------- Group mapping: bid -> (bi, bj0, nb) ------------------
    int rem = bid, bi = 0;
    for (;;) {
        int g = (NTILES - bi + 3) >> 2;
        if (rem < g) break;
        rem -= g; bi++;
    }
    const int bj0 = bi + rem * 4;
    const int nb  = min(4, NTILES - bj0);

    // ---------------- Load A band + classes (once per group) ---------------
    {
        const uint4* Ag = (const uint4*)(g_xb + (size_t)bi * TILE * DDIM);
        #pragma unroll
        for (int r = 0; r < 4; r++) {
            int idx = tid + r * 256;
            int row = idx >> 3;
            int ch  = idx & 7;
            *(uint4*)(sA + row * ROWB + ch * 16) = Ag[idx];
        }
        if (tid < TILE) csi[tid] = cls[bi * TILE + tid];
        // column classes for all nb tiles (512 ints; some lanes out of range)
        for (int q = tid; q < nb * TILE; q += 256)
            csj[q] = cls[bj0 * TILE + q];
    }

    // ---------------- Prefetch B(0) -----------------------------------------
    uint32_t bufu[3] = { smem_u32(sB), smem_u32(sB + BUFB),
                         smem_u32(sB + 2 * BUFB) };
    {
        const char* src = (const char*)(g_xb + (size_t)bj0 * TILE * DDIM);
        #pragma unroll
        for (int r = 0; r < 4; r++) {
            int idx = tid + r * 256;
            int row = idx >> 3;
            int ch  = idx & 7;
            cpa16(bufu[0] + row * ROWB + ch * 16, src + idx * 16);
        }
    }
    CPA_COMMIT();

    const uint32_t a_base = smem_u32(sA);
    const int wm = wid & 3;
    const int wn = wid >> 2;
    const uint32_t a_lane_off =
        (uint32_t)((wm * 32 + (lane & 15)) * ROWB + ((lane >> 4) << 4));
    const uint32_t b_lane_off =
        (uint32_t)((wn * 64 + (lane & 7) + ((lane >> 4) << 3)) * ROWB +
                   (((lane >> 3) & 1) << 4));
    const float MC = MARGIN - 1.0f;
    const int quad = lane >> 2;
    const int tq   = lane & 3;

    float lsum = 0.0f;

    for (int t = 0; t < nb; t++) {
        // Prefetch next B into buf[(t+1)%3]; wait for current.
        if (t + 1 < nb) {
            const char* src =
                (const char*)(g_xb + (size_t)(bj0 + t + 1) * TILE * DDIM);
            uint32_t dst = bufu[(t + 1) % 3];
            #pragma unroll
            for (int r = 0; r < 4; r++) {
                int idx = tid + r * 256;
                int row = idx >> 3;
                int ch  = idx & 7;
                cpa16(dst + row * ROWB + ch * 16, src + idx * 16);
            }
            CPA_COMMIT();
            CPA_WAIT(1);
        } else {
            CPA_WAIT(0);
        }
        __syncthreads();

        const uint32_t b_base = bufu[t % 3];

        float c[2][8][4];
        #pragma unroll
        for (int m = 0; m < 2; m++)
            #pragma unroll
            for (int n = 0; n < 8; n++)
                #pragma unroll
                for (int e = 0; e < 4; e++) c[m][n][e] = 0.0f;

        #pragma unroll
        for (int k = 0; k < 4; k++) {
            uint32_t a[2][4];
            #pragma unroll
            for (int m = 0; m < 2; m++)
                ldsm_x4(a[m][0], a[m][1], a[m][2], a[m][3],
                        a_base + a_lane_off + m * 16 * ROWB + k * 32);
            uint32_t b[8][2];
            #pragma unroll
            for (int q = 0; q < 4; q++) {
                uint32_t r0, r1, r2, r3;
                ldsm_x4(r0, r1, r2, r3,
                        b_base + b_lane_off + q * 16 * ROWB + k * 32);
                b[q * 2 + 0][0] = r0; b[q * 2 + 0][1] = r1;
                b[q * 2 + 1][0] = r2; b[q * 2 + 1][1] = r3;
            }
            #pragma unroll
            for (int m = 0; m < 2; m++)
                #pragma unroll
                for (int n = 0; n < 8; n++)
                    mma_16816(c[m][n], a[m], b[n][0], b[n][1]);
        }

        // ---- Hinge epilogue on fragments ----
        const int* cjt = csj + t * TILE;
        float l0 = 0.0f, l1 = 0.0f;
        #pragma unroll
        for (int m = 0; m < 2; m++) {
            const int ci0 = csi[wm * 32 + m * 16 + quad];
            const int ci1 = csi[wm * 32 + m * 16 + quad + 8];
            #pragma unroll
            for (int n = 0; n < 8; n++) {
                const int colb = wn * 64 + n * 8 + tq * 2;
                const int cj0  = cjt[colb];
                const int cj1  = cjt[colb + 1];
                float v0 = c[m][n][0], v1 = c[m][n][1];
                float v2 = c[m][n][2], v3 = c[m][n][3];
                l0 += (ci0 == cj0) ? (1.0f - v0) : fmaxf(v0 + MC, 0.0f);
                l1 += (ci0 == cj1) ? (1.0f - v1) : fmaxf(v1 + MC, 0.0f);
                l0 += (ci1 == cj0) ? (1.0f - v2) : fmaxf(v2 + MC, 0.0f);
                l1 += (ci1 == cj1) ? (1.0f - v3) : fmaxf(v3 + MC, 0.0f);
            }
        }
        float tl = l0 + l1;
        lsum += (bj0 + t == bi) ? tl : 2.0f * tl;   // off-diag counted twice
    }

    // ---------------- Group reduce + finalize --------------------------------
    #pragma unroll
    for (int o = 16; o; o >>= 1) lsum += __shfl_xor_sync(0xffffffffu, lsum, o);
    if (lane == 0) red[wid] = lsum;
    __syncthreads();
    if (tid == 0) {
        float tt = 0.0f;
        #pragma unroll
        for (int w = 0; w < 8; w++) tt += red[w];
        atomicAdd(&g_accum, (double)tt);
        __threadfence();
        unsigned old = atomicAdd(&g_done_ctr, 1u);
        if (old == (unsigned)(NGROUPS - 1)) {
            double a = atomicAdd(&g_accum, 0.0);
            out[0] = (float)(a / ((double)NROWS * (double)NROWS));
            g_accum     = 0.0;
            g_done_ctr  = 0u;
            g_prep_done = 0u;
        }
    }
}

extern "C" void kernel_launch(void* const* d_in, const int* in_sizes, int n_in,
                              void* d_out, int out_size) {
    const float* bottleneck = (const float*)d_in[0];
    const int*   class_map  = (const int*)d_in[1];
    float*       out        = (float*)d_out;

    cudaFuncSetAttribute(fused_kernel,
                         cudaFuncAttributeMaxDynamicSharedMemorySize,
                         SMEM_TOTAL);
    fused_kernel<<<NGROUPS, 256, SMEM_TOTAL>>>(bottleneck, class_map, out);
}